// round 15
// baseline (speedup 1.0000x reference)
#include <cuda_runtime.h>
#include <cuda_fp16.h>
#include <math.h>
#include <stdint.h>

// ----------------------------------------------------------------------------
// DecoderLSTMWithAttention — R15:
//   - logits GEMM: mbarrier free-running pipeline (R14) with k32 chunks —
//     halves per-chunk barrier protocol cost (R14 profile: alu 19%, issue 31%
//     = mbarrier wait/arrive overhead). 3 stages x 24KB dynamic smem.
//   - rest identical to R14 (fused prep + ctxW fold, gpre K=512, R7 chain,
//     tile-max argmax with exact-fp32 recheck).
// ----------------------------------------------------------------------------

#define Bb 128
#define Hh 512
#define Tt 27
#define Vv 30000
#define NBLK 128
#define VPAD 30208
#define NT256 118
#define TMSTRIDE 120
#define STAGE_B 24576
#define LOG_SMEM (3 * STAGE_B + 64)

// scratch (device globals: no allocations allowed)
__device__ float g_v0[512];
__device__ float g_v1[512];
__device__ float g_q[512];
__device__ float g_ctx[128 * 512];
__device__ float g_ctxW[128 * 2048];
__device__ float g_Gpre[27u * 128u * 2048u];
__device__ float g_H2[27u * 128u * 512u];
__device__ float g_c[2][128 * 512];
__device__ float g_part[8u * 128u * 2048u];
__device__ unsigned g_bar_cnt;
__device__ unsigned g_bar_gen;
__device__ float g_tilemax[3456u * TMSTRIDE];
__device__ __half g_Ah[3456u * 512u];
__device__ __half g_Wh[(unsigned)VPAD * 512u];

// ---------------- packed fp32x2 helpers ----------------
__device__ __forceinline__ unsigned long long pack2(float x) {
    unsigned long long r;
    asm("mov.b64 %0, {%1, %1};" : "=l"(r) : "f"(x));
    return r;
}
__device__ __forceinline__ void ffma2(unsigned long long& d, unsigned long long a, unsigned long long b) {
    asm("fma.rn.f32x2 %0, %1, %2, %0;" : "+l"(d) : "l"(a), "l"(b));
}
__device__ __forceinline__ float2 unpack2(unsigned long long v) {
    float lo, hi;
    asm("mov.b64 {%0, %1}, %2;" : "=f"(lo), "=f"(hi) : "l"(v));
    return make_float2(lo, hi);
}

// ---------------- ptx helpers ----------------------------------------------------
__device__ __forceinline__ uint32_t smem_u32(const void* p) {
    uint32_t a;
    asm("{ .reg .u64 t; cvta.to.shared.u64 t, %1; cvt.u32.u64 %0, t; }" : "=r"(a) : "l"(p));
    return a;
}
__device__ __forceinline__ void cp16(uint32_t dst, const void* src) {
    asm volatile("cp.async.cg.shared.global [%0], [%1], 16;" :: "r"(dst), "l"(src));
}
__device__ __forceinline__ void ldm_x4(uint32_t* r, uint32_t addr) {
    asm volatile("ldmatrix.sync.aligned.m8n8.x4.shared.b16 {%0,%1,%2,%3}, [%4];"
        : "=r"(r[0]), "=r"(r[1]), "=r"(r[2]), "=r"(r[3]) : "r"(addr));
}
__device__ __forceinline__ void mma_fp16(float* d, const uint32_t* a, const uint32_t* b) {
    asm volatile("mma.sync.aligned.m16n8k16.row.col.f32.f16.f16.f32 "
        "{%0,%1,%2,%3}, {%4,%5,%6,%7}, {%8,%9}, {%0,%1,%2,%3};"
        : "+f"(d[0]), "+f"(d[1]), "+f"(d[2]), "+f"(d[3])
        : "r"(a[0]), "r"(a[1]), "r"(a[2]), "r"(a[3]), "r"(b[0]), "r"(b[1]));
}
__device__ __forceinline__ unsigned fenc(float x) {
    int i = __float_as_int(x);
    return (i >= 0) ? ((unsigned)i | 0x80000000u) : ~(unsigned)i;
}
__device__ __forceinline__ float fdec(unsigned e) {
    int i = (e & 0x80000000u) ? (int)(e & 0x7fffffffu) : ~(int)e;
    return __int_as_float(i);
}

// ---------------- mbarrier helpers (sm_80+ baseline PTX) ------------------------
#define MB_INIT(a, c) asm volatile("mbarrier.init.shared.b64 [%0], %1;" :: "r"(a), "r"(c) : "memory")
#define MB_ARRIVE(a)  asm volatile("mbarrier.arrive.shared.b64 _, [%0];" :: "r"(a) : "memory")
#define CP_MBAR_ARRIVE(a) asm volatile("cp.async.mbarrier.arrive.noinc.shared.b64 [%0];" :: "r"(a) : "memory")
__device__ __forceinline__ void mbar_wait(uint32_t mbar, uint32_t parity) {
    uint32_t done;
    asm volatile(
        "{\n\t.reg .pred p;\n\t"
        "mbarrier.try_wait.parity.acquire.cta.shared::cta.b64 p, [%1], %2;\n\t"
        "selp.b32 %0, 1, 0, p;\n\t}"
        : "=r"(done) : "r"(mbar), "r"(parity) : "memory");
    if (!done) {
        asm volatile(
            "{\n\t.reg .pred P1;\n\t"
            "W_%=:\n\t"
            "mbarrier.try_wait.parity.acquire.cta.shared::cta.b64 P1, [%0], %1, 0x989680;\n\t"
            "@P1 bra.uni D_%=;\n\t"
            "bra.uni W_%=;\n\t"
            "D_%=:\n\t}"
            :: "r"(mbar), "r"(parity) : "memory");
    }
}

// ---------------- software grid barrier (tight spin, launch-relative) ----------
__device__ __forceinline__ void gsync(unsigned target) {
    __syncthreads();
    if (threadIdx.x == 0) {
        __threadfence();
        unsigned prev = atomicAdd(&g_bar_cnt, 1u);
        if (prev == NBLK - 1) {
            g_bar_cnt = 0;
            __threadfence();
            *(volatile unsigned*)&g_bar_gen = target;
        } else {
            volatile unsigned* vg = (volatile unsigned*)&g_bar_gen;
            while ((int)(*vg - target) < 0) {}
        }
        __threadfence();
    }
    __syncthreads();
}

// ---------------- FFMA2 GEMM micro-kernel ---------------------------------------
__device__ __forceinline__ void tile_fma(const float* As, const float* Bs, int tr, int tc,
                                         unsigned long long acc[8][4]) {
    #pragma unroll
    for (int kk = 0; kk < 16; kk++) {
        float4 a0 = *(const float4*)(As + kk * 128 + tr * 4);
        float4 a1 = *(const float4*)(As + kk * 128 + 64 + tr * 4);
        ulonglong2 b0 = *(const ulonglong2*)(Bs + kk * 128 + tc * 4);
        ulonglong2 b1 = *(const ulonglong2*)(Bs + kk * 128 + 64 + tc * 4);
        unsigned long long pb0 = b0.x, pb1 = b0.y, pb2 = b1.x, pb3 = b1.y;
        float av[8] = {a0.x, a0.y, a0.z, a0.w, a1.x, a1.y, a1.z, a1.w};
        #pragma unroll
        for (int i = 0; i < 8; i++) {
            unsigned long long pa = pack2(av[i]);
            ffma2(acc[i][0], pa, pb0);
            ffma2(acc[i][1], pa, pb1);
            ffma2(acc[i][2], pa, pb2);
            ffma2(acc[i][3], pa, pb3);
        }
    }
}
__device__ __forceinline__ void stT(float* S, int r, int lc, float4 v) {
    float* d = S + r;
    d[(lc + 0) * 128] = v.x;
    d[(lc + 1) * 128] = v.y;
    d[(lc + 2) * 128] = v.z;
    d[(lc + 3) * 128] = v.w;
}

// ---------------- fused prep: convW -> matvec fold -> attention -> ctxW ---------
__global__ void __launch_bounds__(256) fused_prep(
    const float* __restrict__ w_att, const float* __restrict__ W4,
    const float* __restrict__ W3, const float* __restrict__ W2,
    const float* __restrict__ W1, const float* __restrict__ enc,
    const float* __restrict__ Wout, const float* __restrict__ Wih,
    const float* __restrict__ bih, const float* __restrict__ bhh) {
    __shared__ float S[1024];
    __shared__ float Wt[16 * 512];
    int tid = threadIdx.x, bid = blockIdx.x;
    unsigned gen0 = *(volatile unsigned*)&g_bar_gen;

    // phase A: W_out -> fp16 (grid-stride; pad region zeroed)
    {
        int nW = Vv * 512;
        int stride = NBLK * 256 * 4;
        for (int i0 = (bid * 256 + tid) * 4; i0 < VPAD * 512; i0 += stride) {
            if (i0 + 3 < nW) {
                float4 v = *(const float4*)(Wout + i0);
                __half2* dp = (__half2*)(g_Wh + i0);
                dp[0] = __floats2half2_rn(v.x, v.y);
                dp[1] = __floats2half2_rn(v.z, v.w);
            } else {
                #pragma unroll
                for (int u = 0; u < 4; u++) {
                    int i = i0 + u;
                    g_Wh[i] = __float2half_rn(i < nW ? Wout[i] : 0.f);
                }
            }
        }
    }

    // phases 0..3: fold q = W1[:, :H]^T W2^T W3^T W4^T w
    const float* Ws[4] = {W4, W3, W2, W1};
    #pragma unroll 1
    for (int p = 0; p < 4; p++) {
        const float* W = Ws[p];
        int stride = (p == 3) ? 1024 : 512;
        const float* vin = (p == 0) ? w_att : ((p == 2) ? g_v1 : g_v0);
        float* vout = (p == 0) ? g_v0 : ((p == 1) ? g_v1 : ((p == 2) ? g_v0 : g_q));
        int k = bid * 4 + (tid & 3);
        int s = tid >> 2;
        float a = 0.f;
        #pragma unroll
        for (int u = 0; u < 8; u++) {
            int j = s * 8 + u;
            a += __ldcg(vin + j) * W[(size_t)j * stride + k];
        }
        S[tid] = a;
        __syncthreads();
        if (tid < 4) {
            float acc = 0.f;
            for (int s2 = 0; s2 < 64; s2++) acc += S[tid + 4 * s2];
            vout[bid * 4 + tid] = acc;
        }
        gsync(gen0 + 1 + p);
    }

    // attention for batch b = bid
    {
        float* sq = &S[0];
        float* sc = &S[512];
        int b = bid;
        sq[tid] = __ldcg(g_q + tid);
        sq[tid + 256] = __ldcg(g_q + tid + 256);
        __syncthreads();
        int w = tid >> 5, lane = tid & 31;
        for (int s = w; s < 80; s += 8) {
            const float* e = enc + ((size_t)b * 80 + s) * 512;
            float acc = 0.f;
            for (int k = lane; k < 512; k += 32) acc += e[k] * sq[k];
            #pragma unroll
            for (int o = 16; o; o >>= 1) acc += __shfl_xor_sync(0xffffffffu, acc, o);
            if (lane == 0) sc[s] = acc;
        }
        __syncthreads();
        if (tid < 32) {
            float m = -1e30f;
            for (int s = tid; s < 80; s += 32) m = fmaxf(m, sc[s]);
            #pragma unroll
            for (int o = 16; o; o >>= 1) m = fmaxf(m, __shfl_xor_sync(0xffffffffu, m, o));
            float sum = 0.f;
            for (int s = tid; s < 80; s += 32) { float e = expf(sc[s] - m); sc[s] = e; sum += e; }
            #pragma unroll
            for (int o = 16; o; o >>= 1) sum += __shfl_xor_sync(0xffffffffu, sum, o);
            float inv = 1.f / sum;
            for (int s = tid; s < 80; s += 32) sc[s] *= inv;
        }
        __syncthreads();
        for (int k = tid; k < 512; k += 256) {
            float a = 0.f;
            #pragma unroll 8
            for (int s = 0; s < 80; s++) a += sc[s] * enc[((size_t)b * 80 + s) * 512 + k];
            g_ctx[b * 512 + k] = a;
        }
    }
    gsync(gen0 + 5);

    // phase ctxW: block bid computes ctxW[:, 16*bid .. 16*bid+16)
    {
        int nb = bid * 16;
        for (int i = 0; i < 32; i++) {
            int idx = i * 256 + tid;
            int row = idx >> 9, col = idx & 511;
            Wt[row * 512 + col] = Wih[(size_t)(nb + row) * 1024 + 512 + col];
        }
        __syncthreads();
        int nl = tid & 15;
        int bg = tid >> 4;
        float bias = bih[nb + nl] + bhh[nb + nl];
        #pragma unroll
        for (int i = 0; i < 8; i++) {
            int b = bg * 8 + i;
            const float4* cr = (const float4*)(g_ctx + b * 512);
            const float4* wr = (const float4*)(Wt + nl * 512);
            float a0 = 0.f, a1 = 0.f, a2 = 0.f, a3 = 0.f;
            #pragma unroll 16
            for (int q = 0; q < 128; q++) {
                float4 c = cr[q];
                float4 w = wr[q];
                a0 += c.x * w.x; a1 += c.y * w.y; a2 += c.z * w.z; a3 += c.w * w.w;
            }
            g_ctxW[b * 2048 + nb + nl] = (a0 + a1) + (a2 + a3) + bias;
        }
    }
}

// ---------------- Gpre = emb(tok) @ WihA^T + ctxW (432 blocks, occ 2) -----------
__global__ void __launch_bounds__(256, 2) gpre_gemm(
    const int* __restrict__ targets, const float* __restrict__ emb,
    const float* __restrict__ Wih) {
    __shared__ float As[2][16 * 128];
    __shared__ float Bs[2][16 * 128];
    __shared__ int tok[128];
    int t = blockIdx.y;
    int nbase = blockIdx.x * 128;
    int tid = threadIdx.x;
    if (tid < 128) tok[tid] = targets[tid * 28 + t];
    __syncthreads();
    int tr = tid >> 4, tc = tid & 15;
    int lr = tid >> 2, lc = (tid & 3) << 2;
    unsigned long long acc[8][4];
    #pragma unroll
    for (int i = 0; i < 8; i++)
        #pragma unroll
        for (int j = 0; j < 4; j++) acc[i][j] = 0ull;

    float4 ra0, ra1, rb0, rb1;
    ra0 = *(const float4*)(emb + (size_t)tok[lr] * 512 + lc);
    ra1 = *(const float4*)(emb + (size_t)tok[lr + 64] * 512 + lc);
    rb0 = *(const float4*)(Wih + (size_t)(nbase + lr) * 1024 + lc);
    rb1 = *(const float4*)(Wih + (size_t)(nbase + lr + 64) * 1024 + lc);
    stT(As[0], lr, lc, ra0); stT(As[0], lr + 64, lc, ra1);
    stT(Bs[0], lr, lc, rb0); stT(Bs[0], lr + 64, lc, rb1);
    __syncthreads();

    int cur = 0;
    for (int kt = 0; kt < 32; kt++) {
        if (kt < 31) {
            int k0 = (kt + 1) * 16;
            ra0 = *(const float4*)(emb + (size_t)tok[lr] * 512 + k0 + lc);
            ra1 = *(const float4*)(emb + (size_t)tok[lr + 64] * 512 + k0 + lc);
            rb0 = *(const float4*)(Wih + (size_t)(nbase + lr) * 1024 + k0 + lc);
            rb1 = *(const float4*)(Wih + (size_t)(nbase + lr + 64) * 1024 + k0 + lc);
        }
        tile_fma(As[cur], Bs[cur], tr, tc, acc);
        if (kt < 31) {
            stT(As[cur ^ 1], lr, lc, ra0); stT(As[cur ^ 1], lr + 64, lc, ra1);
            stT(Bs[cur ^ 1], lr, lc, rb0); stT(Bs[cur ^ 1], lr + 64, lc, rb1);
        }
        __syncthreads();
        cur ^= 1;
    }
    #pragma unroll
    for (int i = 0; i < 8; i++) {
        int b = (i < 4) ? tr * 4 + i : 64 + tr * 4 + (i - 4);
        float* dst = g_Gpre + ((size_t)t * 128 + b) * 2048;
        const float* cw = g_ctxW + (size_t)b * 2048;
        #pragma unroll
        for (int j = 0; j < 4; j++) {
            int nc = nbase + ((j >> 1) << 6) + tc * 4 + ((j & 1) << 1);
            float2 v = unpack2(acc[i][j]);
            dst[nc] = v.x + cw[nc];
            dst[nc + 1] = v.y + cw[nc + 1];
        }
    }
}

// ---------------- persistent LSTM chain: W_hh smem-resident (R7) ----------------
__global__ void __launch_bounds__(256, 1) lstm_chain(const float* __restrict__ elhs,
                                                     const float* __restrict__ Whh) {
    __shared__ float SB[64 * 128];
    __shared__ float As[2][16 * 128];
    int tid = threadIdx.x;
    int nbase = (blockIdx.x & 15) * 128;
    int ks = blockIdx.x >> 4;
    int kbeg = ks * 64;
    int tr = tid >> 4, tc = tid & 15;
    int lr = tid >> 2, lc = (tid & 3) << 2;

    #pragma unroll
    for (int kc = 0; kc < 4; kc++)
        #pragma unroll
        for (int p = 0; p < 2; p++) {
            float4 v = *(const float4*)(Whh + (size_t)(nbase + lr + p * 64) * 512 + kbeg + kc * 16 + lc);
            stT(SB + kc * 16 * 128, lr + p * 64, lc, v);
        }
    unsigned epoch = *(volatile unsigned*)&g_bar_gen;
    __syncthreads();

    for (int t = 0; t < 27; t++) {
        const float* A = (t == 0) ? elhs : (g_H2 + (size_t)(t - 1) * 128 * 512);
        unsigned long long acc[8][4];
        #pragma unroll
        for (int i = 0; i < 8; i++)
            #pragma unroll
            for (int j = 0; j < 4; j++) acc[i][j] = 0ull;

        float4 ra0, ra1;
        ra0 = *(const float4*)(A + (size_t)lr * 512 + kbeg + lc);
        ra1 = *(const float4*)(A + (size_t)(lr + 64) * 512 + kbeg + lc);
        stT(As[0], lr, lc, ra0); stT(As[0], lr + 64, lc, ra1);
        __syncthreads();
        int cur = 0;
        #pragma unroll
        for (int kt = 0; kt < 4; kt++) {
            if (kt < 3) {
                int k0 = kbeg + (kt + 1) * 16;
                ra0 = *(const float4*)(A + (size_t)lr * 512 + k0 + lc);
                ra1 = *(const float4*)(A + (size_t)(lr + 64) * 512 + k0 + lc);
            }
            tile_fma(As[cur], SB + kt * 16 * 128, tr, tc, acc);
            if (kt < 3) {
                stT(As[cur ^ 1], lr, lc, ra0); stT(As[cur ^ 1], lr + 64, lc, ra1);
            }
            __syncthreads();
            cur ^= 1;
        }
        #pragma unroll
        for (int i = 0; i < 8; i++) {
            int b = (i < 4) ? tr * 4 + i : 64 + tr * 4 + (i - 4);
            float* dst = g_part + ((size_t)ks * 128 + b) * 2048;
            #pragma unroll
            for (int j = 0; j < 4; j++) {
                int nc = nbase + ((j >> 1) << 6) + tc * 4 + ((j & 1) << 1);
                float2 v = unpack2(acc[i][j]);
                dst[nc] = v.x;
                dst[nc + 1] = v.y;
            }
        }
        gsync(++epoch);

        #pragma unroll
        for (int e = 0; e < 2; e++) {
            int idx = e * 32768 + blockIdx.x * 256 + tid;
            int b = idx >> 9, j = idx & 511;
            const float* gp = g_Gpre + ((size_t)t * 128 + b) * 2048;
            float gi = gp[j], gf = gp[j + 512], gg = gp[j + 1024], go = gp[j + 1536];
            #pragma unroll
            for (int kk = 0; kk < 8; kk++) {
                const float* pp = g_part + ((size_t)kk * 128 + b) * 2048;
                gi += __ldcg(pp + j);
                gf += __ldcg(pp + j + 512);
                gg += __ldcg(pp + j + 1024);
                go += __ldcg(pp + j + 1536);
            }
            float cprev = (t == 0) ? 0.f : __ldcg(&g_c[(t - 1) & 1][b * 512 + j]);
            float si = 1.f / (1.f + expf(-gi));
            float sf = 1.f / (1.f + expf(-gf));
            float so = 1.f / (1.f + expf(-go));
            float c2 = sf * cprev + si * tanhf(gg);
            float h2 = so * tanhf(c2);
            g_c[t & 1][b * 512 + j] = c2;
            size_t hidx = (size_t)t * 128 * 512 + b * 512 + j;
            g_H2[hidx] = h2;
            g_Ah[hidx] = __float2half_rn(h2);
        }
        gsync(++epoch);
    }
}

// ---------------- HMMA logits GEMM: 128x256, k32 mbarrier pipeline --------------
// stage (24KB): A0@0, A1@4096, B0@8192, B1@16384 (two k16 sub-tiles)
// mbarriers at +3*STAGE_B: full[s] @ +8s, empty[s] @ +24+8s
__global__ void __launch_bounds__(512, 1) hmma_logits(const float* __restrict__ bout,
                                                      float* __restrict__ out) {
    extern __shared__ char lsm[];
    int tid = threadIdx.x;
    int lane = tid & 31, wid = tid >> 5;     // 16 warps
    int wm = wid & 1, wn = wid >> 1;         // 2(M) x 8(N)
    int ntile = blockIdx.x, mtile = blockIdx.y;
    int mbase = mtile * 128, nbase = ntile * 256;

    const __half* gA = g_Ah + (size_t)mbase * 512;
    const __half* gB = g_Wh + (size_t)nbase * 512;

    int rA = tid >> 1, kbA = tid & 1;                    // A loader (tid<256)
    int rB = tid >> 1, kbB = tid & 1;                    // B loader (all)
    uint32_t dA = (uint32_t)(((rA >> 3) * 2 + kbA) * 128 + (rA & 7) * 16);
    uint32_t dB = (uint32_t)(((rB >> 3) * 2 + kbB) * 128 + (rB & 7) * 16);
    size_t sA = (size_t)rA * 512 + kbA * 8;
    size_t sB = (size_t)rB * 512 + kbB * 8;
    uint32_t sbase = smem_u32(lsm);
    uint32_t mbb = sbase + (uint32_t)(3 * STAGE_B);

    if (tid == 0) {
        #pragma unroll
        for (int s = 0; s < 3; s++) {
            MB_INIT(mbb + 8u * s, 512);
            MB_INIT(mbb + 24u + 8u * s, 16);
        }
    }
    __syncthreads();

    uint32_t a_lane = (uint32_t)(((((lane >> 3) & 1) * 2 + (lane >> 4)) * 128) + (lane & 7) * 16);
    uint32_t b_lane = (uint32_t)((((lane >> 3) & 3) * 128) + (lane & 7) * 16);

    float d[4][4][4];
    #pragma unroll
    for (int i = 0; i < 4; i++)
        #pragma unroll
        for (int j = 0; j < 4; j++)
            #pragma unroll
            for (int q = 0; q < 4; q++) d[i][j][q] = 0.f;

    // producer: fill stage C%3 with k32 chunk C (A: 2 cp16 if tid<256; B: 2 cp16)
    auto produce = [&](int C) {
        int st = C % 3;
        int rr = C / 3;
        if (rr > 0) mbar_wait(mbb + 24u + 8u * st, (unsigned)((rr - 1) & 1));
        uint32_t sb = sbase + (uint32_t)st * STAGE_B;
        size_t ko = (size_t)C * 32;
        cp16(sb + 8192u + dB,  gB + sB + ko);
        cp16(sb + 16384u + dB, gB + sB + ko + 16);
        if (tid < 256) {
            cp16(sb + dA,         gA + sA + ko);
            cp16(sb + 4096u + dA, gA + sA + ko + 16);
        }
        CP_MBAR_ARRIVE(mbb + 8u * st);
    };

    produce(0);
    produce(1);

    for (int c = 0; c < 16; c++) {
        if (c + 2 < 16) produce(c + 2);
        int st = c % 3;
        mbar_wait(mbb + 8u * st, (unsigned)((c / 3) & 1));
        uint32_t sb = sbase + (uint32_t)st * STAGE_B;

        #pragma unroll
        for (int s = 0; s < 2; s++) {
            uint32_t abase = sb + (uint32_t)s * 4096u + a_lane;
            uint32_t bbase = sb + 8192u + (uint32_t)s * 8192u + b_lane;
            uint32_t a[4][4], b[4][2];
            #pragma unroll
            for (int mt = 0; mt < 4; mt++) ldm_x4(a[mt], abase + (uint32_t)((wm * 4 + mt) * 512));
            #pragma unroll
            for (int p = 0; p < 2; p++) {
                uint32_t rr[4];
                ldm_x4(rr, bbase + (uint32_t)((wn * 4 + 2 * p) * 256));
                b[2 * p][0] = rr[0]; b[2 * p][1] = rr[1];
                b[2 * p + 1][0] = rr[2]; b[2 * p + 1][1] = rr[3];
            }
            #pragma unroll
            for (int mt = 0; mt < 4; mt++)
                #pragma unroll
                for (int nt = 0; nt < 4; nt++) mma_fp16(d[mt][nt], a[mt], b[nt]);
        }

        if (lane == 0) MB_ARRIVE(mbb + 24u + 8u * st);
    }

    // epilogue: logits + per-(row,ntile) max (reuse stage smem)
    __syncthreads();
    unsigned* srow = (unsigned*)lsm;
    if (tid < 128) srow[tid] = 0u;
    __syncthreads();

    float rmax[4][2];
    #pragma unroll
    for (int mt = 0; mt < 4; mt++) { rmax[mt][0] = -3.4e38f; rmax[mt][1] = -3.4e38f; }
    #pragma unroll
    for (int nt = 0; nt < 4; nt++) {
        int n = nbase + wn * 32 + nt * 8 + (lane & 3) * 2;
        if (n >= Vv) continue;
        float bx = bout[n], by = bout[n + 1];
        #pragma unroll
        for (int mt = 0; mt < 4; mt++) {
            int m0 = wm * 64 + mt * 16 + (lane >> 2);
            size_t row0 = (size_t)(m0 * 27 + mtile) * Vv;
            size_t row8 = (size_t)((m0 + 8) * 27 + mtile) * Vv;
            float2 v0 = make_float2(d[mt][nt][0] + bx, d[mt][nt][1] + by);
            float2 v1 = make_float2(d[mt][nt][2] + bx, d[mt][nt][3] + by);
            *(float2*)(out + row0 + n) = v0;
            *(float2*)(out + row8 + n) = v1;
            rmax[mt][0] = fmaxf(rmax[mt][0], fmaxf(v0.x, v0.y));
            rmax[mt][1] = fmaxf(rmax[mt][1], fmaxf(v1.x, v1.y));
        }
    }
    #pragma unroll
    for (int mt = 0; mt < 4; mt++) {
        int q = lane >> 2;
        atomicMax(&srow[wm * 64 + mt * 16 + q],     fenc(rmax[mt][0]));
        atomicMax(&srow[wm * 64 + mt * 16 + q + 8], fenc(rmax[mt][1]));
    }
    __syncthreads();
    if (tid < 128)
        g_tilemax[(size_t)(tid * 27 + mtile) * TMSTRIDE + ntile] = fdec(srow[tid]);
}

// ---------------- argmax: tile-max guided scan + exact-fp32 recheck -------------
__global__ void argmax_exact(const float* __restrict__ logits, float* __restrict__ preds,
                             const float* __restrict__ Wout, const float* __restrict__ bout) {
    __shared__ float sv[256];
    __shared__ float hrow[512];
    __shared__ int scand[64];
    __shared__ int tlist[32];
    __shared__ int ncand, ntl;
    __shared__ float bestv;
    __shared__ int besti;
    int rrow = blockIdx.x;
    int tid = threadIdx.x;
    int b = rrow / 27, t = rrow % 27;
    const float* row = logits + (size_t)rrow * Vv;

    float v = (tid < NT256) ? g_tilemax[(size_t)rrow * TMSTRIDE + tid] : -3.4e38f;
    sv[tid] = v;
    __syncthreads();
    for (int o = 128; o; o >>= 1) {
        if (tid < o) sv[tid] = fmaxf(sv[tid], sv[tid + o]);
        __syncthreads();
    }
    float thr = sv[0] - 1e-3f;

    const float* h = g_H2 + ((size_t)t * 128 + b) * 512;
    hrow[tid] = h[tid];
    hrow[tid + 256] = h[tid + 256];
    if (tid == 0) { ncand = 0; ntl = 0; bestv = -3.4e38f; besti = 0x7fffffff; }
    __syncthreads();

    if (tid < NT256 && v >= thr) {
        int p = atomicAdd(&ntl, 1);
        if (p < 32) tlist[p] = tid;
    }
    __syncthreads();
    int ntiles = ntl < 32 ? ntl : 32;

    for (int ti = 0; ti < ntiles; ti++) {
        int n = tlist[ti] * 256 + tid;
        if (n < Vv) {
            float lv = row[n];
            if (lv >= thr) {
                int p = atomicAdd(&ncand, 1);
                if (p < 64) scand[p] = n;
            }
        }
    }
    __syncthreads();
    int nc = ncand < 64 ? ncand : 64;

    for (int ci = 0; ci < nc; ci++) {
        int idx = scand[ci];
        const float* wr = Wout + (size_t)idx * 512;
        float p = 0.f;
        for (int k = tid; k < 512; k += 256) p += hrow[k] * wr[k];
        sv[tid] = p;
        __syncthreads();
        for (int o = 128; o; o >>= 1) {
            if (tid < o) sv[tid] += sv[tid + o];
            __syncthreads();
        }
        if (tid == 0) {
            float ev = sv[0] + bout[idx];
            if (ev > bestv || (ev == bestv && idx < besti)) { bestv = ev; besti = idx; }
        }
        __syncthreads();
    }
    if (tid == 0) preds[rrow] = (float)besti;
}

// -------------------------------------------------------------------------------
extern "C" void kernel_launch(void* const* d_in, const int* in_sizes, int n_in,
                              void* d_out, int out_size) {
    const float* elhs    = (const float*)d_in[0];
    const float* enc     = (const float*)d_in[1];
    const int*   targets = (const int*)d_in[2];
    const float* emb     = (const float*)d_in[3];
    const float* W1      = (const float*)d_in[4];
    const float* W2      = (const float*)d_in[6];
    const float* W3      = (const float*)d_in[8];
    const float* W4      = (const float*)d_in[10];
    const float* w_att   = (const float*)d_in[12];
    const float* W_ih    = (const float*)d_in[13];
    const float* W_hh    = (const float*)d_in[14];
    const float* b_ih    = (const float*)d_in[15];
    const float* b_hh    = (const float*)d_in[16];
    const float* W_out   = (const float*)d_in[17];
    const float* b_out   = (const float*)d_in[18];
    float* out = (float*)d_out;

    // host-side attribute set (idempotent; >48KB dynamic smem)
    cudaFuncSetAttribute(hmma_logits, cudaFuncAttributeMaxDynamicSharedMemorySize, LOG_SMEM);

    // 1: fused convW + fold + attention + ctxW
    fused_prep<<<NBLK, 256>>>(w_att, W4, W3, W2, W1, enc, W_out, W_ih, b_ih, b_hh);

    // 2: Gpre (emb part only, K=512, occ-2, 432 blocks)
    gpre_gemm<<<dim3(16, 27), 256>>>(targets, emb, W_ih);

    // 3: LSTM chain (R7 structure, emits fp16 A)
    lstm_chain<<<NBLK, 256>>>(elhs, W_hh);

    // 4: logits GEMM (fp16, 128x256, k32 mbarrier pipeline)  [profiled slot]
    hmma_logits<<<dim3(NT256, 27), 512, LOG_SMEM>>>(b_out, out);

    // 5: argmax (tile-max guided, 256-wide tiles)
    long long main_sz = (long long)3456 * Vv;
    if ((long long)out_size > main_sz)
        argmax_exact<<<3456, 256>>>(out, out + main_sz, W_out, b_out);
}

// round 16
// speedup vs baseline: 1.0385x; 1.0385x over previous
#include <cuda_runtime.h>
#include <cuda_fp16.h>
#include <math.h>
#include <stdint.h>

// ----------------------------------------------------------------------------
// DecoderLSTMWithAttention — R16:
//   - logits: exact R14 config (k16 mbarrier free-running pipeline, 447us
//     measured best; R15's k32 variant regressed and is reverted)
//   - chain: split-K 8->4 with 64-col N tiles (32 ntiles x 4 ksplits) —
//     halves partials L2 traffic (17->8.4 MB/step) and pointwise gathers
//   - rest as R14: fused prep + ctxW fold, gpre K=512, tile-max argmax
// ----------------------------------------------------------------------------

#define Bb 128
#define Hh 512
#define Tt 27
#define Vv 30000
#define NBLK 128
#define VPAD 30208
#define NT256 118
#define TMSTRIDE 120
#define LOG_SMEM (3 * 12288 + 64)

// scratch (device globals: no allocations allowed)
__device__ float g_v0[512];
__device__ float g_v1[512];
__device__ float g_q[512];
__device__ float g_ctx[128 * 512];
__device__ float g_ctxW[128 * 2048];
__device__ float g_Gpre[27u * 128u * 2048u];
__device__ float g_H2[27u * 128u * 512u];
__device__ float g_c[2][128 * 512];
__device__ float g_part[4u * 128u * 2048u];
__device__ unsigned g_bar_cnt;
__device__ unsigned g_bar_gen;
__device__ float g_tilemax[3456u * TMSTRIDE];
__device__ __half g_Ah[3456u * 512u];
__device__ __half g_Wh[(unsigned)VPAD * 512u];

// ---------------- packed fp32x2 helpers ----------------
__device__ __forceinline__ unsigned long long pack2(float x) {
    unsigned long long r;
    asm("mov.b64 %0, {%1, %1};" : "=l"(r) : "f"(x));
    return r;
}
__device__ __forceinline__ void ffma2(unsigned long long& d, unsigned long long a, unsigned long long b) {
    asm("fma.rn.f32x2 %0, %1, %2, %0;" : "+l"(d) : "l"(a), "l"(b));
}
__device__ __forceinline__ float2 unpack2(unsigned long long v) {
    float lo, hi;
    asm("mov.b64 {%0, %1}, %2;" : "=f"(lo), "=f"(hi) : "l"(v));
    return make_float2(lo, hi);
}

// ---------------- ptx helpers ----------------------------------------------------
__device__ __forceinline__ uint32_t smem_u32(const void* p) {
    uint32_t a;
    asm("{ .reg .u64 t; cvta.to.shared.u64 t, %1; cvt.u32.u64 %0, t; }" : "=r"(a) : "l"(p));
    return a;
}
__device__ __forceinline__ void cp16(uint32_t dst, const void* src) {
    asm volatile("cp.async.cg.shared.global [%0], [%1], 16;" :: "r"(dst), "l"(src));
}
__device__ __forceinline__ void ldm_x4(uint32_t* r, uint32_t addr) {
    asm volatile("ldmatrix.sync.aligned.m8n8.x4.shared.b16 {%0,%1,%2,%3}, [%4];"
        : "=r"(r[0]), "=r"(r[1]), "=r"(r[2]), "=r"(r[3]) : "r"(addr));
}
__device__ __forceinline__ void mma_fp16(float* d, const uint32_t* a, const uint32_t* b) {
    asm volatile("mma.sync.aligned.m16n8k16.row.col.f32.f16.f16.f32 "
        "{%0,%1,%2,%3}, {%4,%5,%6,%7}, {%8,%9}, {%0,%1,%2,%3};"
        : "+f"(d[0]), "+f"(d[1]), "+f"(d[2]), "+f"(d[3])
        : "r"(a[0]), "r"(a[1]), "r"(a[2]), "r"(a[3]), "r"(b[0]), "r"(b[1]));
}
__device__ __forceinline__ unsigned fenc(float x) {
    int i = __float_as_int(x);
    return (i >= 0) ? ((unsigned)i | 0x80000000u) : ~(unsigned)i;
}
__device__ __forceinline__ float fdec(unsigned e) {
    int i = (e & 0x80000000u) ? (int)(e & 0x7fffffffu) : ~(int)e;
    return __int_as_float(i);
}

// ---------------- mbarrier helpers ----------------------------------------------
#define MB_INIT(a, c) asm volatile("mbarrier.init.shared.b64 [%0], %1;" :: "r"(a), "r"(c) : "memory")
#define MB_ARRIVE(a)  asm volatile("mbarrier.arrive.shared.b64 _, [%0];" :: "r"(a) : "memory")
#define CP_MBAR_ARRIVE(a) asm volatile("cp.async.mbarrier.arrive.noinc.shared.b64 [%0];" :: "r"(a) : "memory")
__device__ __forceinline__ void mbar_wait(uint32_t mbar, uint32_t parity) {
    uint32_t done;
    asm volatile(
        "{\n\t.reg .pred p;\n\t"
        "mbarrier.try_wait.parity.acquire.cta.shared::cta.b64 p, [%1], %2;\n\t"
        "selp.b32 %0, 1, 0, p;\n\t}"
        : "=r"(done) : "r"(mbar), "r"(parity) : "memory");
    if (!done) {
        asm volatile(
            "{\n\t.reg .pred P1;\n\t"
            "W_%=:\n\t"
            "mbarrier.try_wait.parity.acquire.cta.shared::cta.b64 P1, [%0], %1, 0x989680;\n\t"
            "@P1 bra.uni D_%=;\n\t"
            "bra.uni W_%=;\n\t"
            "D_%=:\n\t}"
            :: "r"(mbar), "r"(parity) : "memory");
    }
}

// ---------------- software grid barrier ------------------------------------------
__device__ __forceinline__ void gsync(unsigned target) {
    __syncthreads();
    if (threadIdx.x == 0) {
        __threadfence();
        unsigned prev = atomicAdd(&g_bar_cnt, 1u);
        if (prev == NBLK - 1) {
            g_bar_cnt = 0;
            __threadfence();
            *(volatile unsigned*)&g_bar_gen = target;
        } else {
            volatile unsigned* vg = (volatile unsigned*)&g_bar_gen;
            while ((int)(*vg - target) < 0) {}
        }
        __threadfence();
    }
    __syncthreads();
}

// ---------------- FFMA2 micro-kernels ---------------------------------------------
__device__ __forceinline__ void tile_fma(const float* As, const float* Bs, int tr, int tc,
                                         unsigned long long acc[8][4]) {
    #pragma unroll
    for (int kk = 0; kk < 16; kk++) {
        float4 a0 = *(const float4*)(As + kk * 128 + tr * 4);
        float4 a1 = *(const float4*)(As + kk * 128 + 64 + tr * 4);
        ulonglong2 b0 = *(const ulonglong2*)(Bs + kk * 128 + tc * 4);
        ulonglong2 b1 = *(const ulonglong2*)(Bs + kk * 128 + 64 + tc * 4);
        unsigned long long pb0 = b0.x, pb1 = b0.y, pb2 = b1.x, pb3 = b1.y;
        float av[8] = {a0.x, a0.y, a0.z, a0.w, a1.x, a1.y, a1.z, a1.w};
        #pragma unroll
        for (int i = 0; i < 8; i++) {
            unsigned long long pa = pack2(av[i]);
            ffma2(acc[i][0], pa, pb0);
            ffma2(acc[i][1], pa, pb1);
            ffma2(acc[i][2], pa, pb2);
            ffma2(acc[i][3], pa, pb3);
        }
    }
}
// 128M x 64N variant (chain): tc in 0..15, 4 N per thread
__device__ __forceinline__ void tile_fma64(const float* As, const float* Bs, int tr, int tc,
                                           unsigned long long acc[8][2]) {
    #pragma unroll
    for (int kk = 0; kk < 16; kk++) {
        float4 a0 = *(const float4*)(As + kk * 128 + tr * 4);
        float4 a1 = *(const float4*)(As + kk * 128 + 64 + tr * 4);
        ulonglong2 b0 = *(const ulonglong2*)(Bs + kk * 64 + tc * 4);
        unsigned long long pb0 = b0.x, pb1 = b0.y;
        float av[8] = {a0.x, a0.y, a0.z, a0.w, a1.x, a1.y, a1.z, a1.w};
        #pragma unroll
        for (int i = 0; i < 8; i++) {
            unsigned long long pa = pack2(av[i]);
            ffma2(acc[i][0], pa, pb0);
            ffma2(acc[i][1], pa, pb1);
        }
    }
}
__device__ __forceinline__ void stT(float* S, int r, int lc, float4 v) {
    float* d = S + r;
    d[(lc + 0) * 128] = v.x;
    d[(lc + 1) * 128] = v.y;
    d[(lc + 2) * 128] = v.z;
    d[(lc + 3) * 128] = v.w;
}

// ---------------- fused prep: convW -> matvec fold -> attention -> ctxW ---------
__global__ void __launch_bounds__(256) fused_prep(
    const float* __restrict__ w_att, const float* __restrict__ W4,
    const float* __restrict__ W3, const float* __restrict__ W2,
    const float* __restrict__ W1, const float* __restrict__ enc,
    const float* __restrict__ Wout, const float* __restrict__ Wih,
    const float* __restrict__ bih, const float* __restrict__ bhh) {
    __shared__ float S[1024];
    __shared__ float Wt[16 * 512];
    int tid = threadIdx.x, bid = blockIdx.x;
    unsigned gen0 = *(volatile unsigned*)&g_bar_gen;

    // phase A: W_out -> fp16
    {
        int nW = Vv * 512;
        int stride = NBLK * 256 * 4;
        for (int i0 = (bid * 256 + tid) * 4; i0 < VPAD * 512; i0 += stride) {
            if (i0 + 3 < nW) {
                float4 v = *(const float4*)(Wout + i0);
                __half2* dp = (__half2*)(g_Wh + i0);
                dp[0] = __floats2half2_rn(v.x, v.y);
                dp[1] = __floats2half2_rn(v.z, v.w);
            } else {
                #pragma unroll
                for (int u = 0; u < 4; u++) {
                    int i = i0 + u;
                    g_Wh[i] = __float2half_rn(i < nW ? Wout[i] : 0.f);
                }
            }
        }
    }

    // phases 0..3: fold q
    const float* Ws[4] = {W4, W3, W2, W1};
    #pragma unroll 1
    for (int p = 0; p < 4; p++) {
        const float* W = Ws[p];
        int stride = (p == 3) ? 1024 : 512;
        const float* vin = (p == 0) ? w_att : ((p == 2) ? g_v1 : g_v0);
        float* vout = (p == 0) ? g_v0 : ((p == 1) ? g_v1 : ((p == 2) ? g_v0 : g_q));
        int k = bid * 4 + (tid & 3);
        int s = tid >> 2;
        float a = 0.f;
        #pragma unroll
        for (int u = 0; u < 8; u++) {
            int j = s * 8 + u;
            a += __ldcg(vin + j) * W[(size_t)j * stride + k];
        }
        S[tid] = a;
        __syncthreads();
        if (tid < 4) {
            float acc = 0.f;
            for (int s2 = 0; s2 < 64; s2++) acc += S[tid + 4 * s2];
            vout[bid * 4 + tid] = acc;
        }
        gsync(gen0 + 1 + p);
    }

    // attention (b = bid)
    {
        float* sq = &S[0];
        float* sc = &S[512];
        int b = bid;
        sq[tid] = __ldcg(g_q + tid);
        sq[tid + 256] = __ldcg(g_q + tid + 256);
        __syncthreads();
        int w = tid >> 5, lane = tid & 31;
        for (int s = w; s < 80; s += 8) {
            const float* e = enc + ((size_t)b * 80 + s) * 512;
            float acc = 0.f;
            for (int k = lane; k < 512; k += 32) acc += e[k] * sq[k];
            #pragma unroll
            for (int o = 16; o; o >>= 1) acc += __shfl_xor_sync(0xffffffffu, acc, o);
            if (lane == 0) sc[s] = acc;
        }
        __syncthreads();
        if (tid < 32) {
            float m = -1e30f;
            for (int s = tid; s < 80; s += 32) m = fmaxf(m, sc[s]);
            #pragma unroll
            for (int o = 16; o; o >>= 1) m = fmaxf(m, __shfl_xor_sync(0xffffffffu, m, o));
            float sum = 0.f;
            for (int s = tid; s < 80; s += 32) { float e = expf(sc[s] - m); sc[s] = e; sum += e; }
            #pragma unroll
            for (int o = 16; o; o >>= 1) sum += __shfl_xor_sync(0xffffffffu, sum, o);
            float inv = 1.f / sum;
            for (int s = tid; s < 80; s += 32) sc[s] *= inv;
        }
        __syncthreads();
        for (int k = tid; k < 512; k += 256) {
            float a = 0.f;
            #pragma unroll 8
            for (int s = 0; s < 80; s++) a += sc[s] * enc[((size_t)b * 80 + s) * 512 + k];
            g_ctx[b * 512 + k] = a;
        }
    }
    gsync(gen0 + 5);

    // ctxW: block bid computes ctxW[:, 16*bid .. +16)
    {
        int nb = bid * 16;
        for (int i = 0; i < 32; i++) {
            int idx = i * 256 + tid;
            int row = idx >> 9, col = idx & 511;
            Wt[row * 512 + col] = Wih[(size_t)(nb + row) * 1024 + 512 + col];
        }
        __syncthreads();
        int nl = tid & 15;
        int bg = tid >> 4;
        float bias = bih[nb + nl] + bhh[nb + nl];
        #pragma unroll
        for (int i = 0; i < 8; i++) {
            int b = bg * 8 + i;
            const float4* cr = (const float4*)(g_ctx + b * 512);
            const float4* wr = (const float4*)(Wt + nl * 512);
            float a0 = 0.f, a1 = 0.f, a2 = 0.f, a3 = 0.f;
            #pragma unroll 16
            for (int q = 0; q < 128; q++) {
                float4 c = cr[q];
                float4 w = wr[q];
                a0 += c.x * w.x; a1 += c.y * w.y; a2 += c.z * w.z; a3 += c.w * w.w;
            }
            g_ctxW[b * 2048 + nb + nl] = (a0 + a1) + (a2 + a3) + bias;
        }
    }
}

// ---------------- Gpre = emb(tok) @ WihA^T + ctxW (432 blocks, occ 2) -----------
__global__ void __launch_bounds__(256, 2) gpre_gemm(
    const int* __restrict__ targets, const float* __restrict__ emb,
    const float* __restrict__ Wih) {
    __shared__ float As[2][16 * 128];
    __shared__ float Bs[2][16 * 128];
    __shared__ int tok[128];
    int t = blockIdx.y;
    int nbase = blockIdx.x * 128;
    int tid = threadIdx.x;
    if (tid < 128) tok[tid] = targets[tid * 28 + t];
    __syncthreads();
    int tr = tid >> 4, tc = tid & 15;
    int lr = tid >> 2, lc = (tid & 3) << 2;
    unsigned long long acc[8][4];
    #pragma unroll
    for (int i = 0; i < 8; i++)
        #pragma unroll
        for (int j = 0; j < 4; j++) acc[i][j] = 0ull;

    float4 ra0, ra1, rb0, rb1;
    ra0 = *(const float4*)(emb + (size_t)tok[lr] * 512 + lc);
    ra1 = *(const float4*)(emb + (size_t)tok[lr + 64] * 512 + lc);
    rb0 = *(const float4*)(Wih + (size_t)(nbase + lr) * 1024 + lc);
    rb1 = *(const float4*)(Wih + (size_t)(nbase + lr + 64) * 1024 + lc);
    stT(As[0], lr, lc, ra0); stT(As[0], lr + 64, lc, ra1);
    stT(Bs[0], lr, lc, rb0); stT(Bs[0], lr + 64, lc, rb1);
    __syncthreads();

    int cur = 0;
    for (int kt = 0; kt < 32; kt++) {
        if (kt < 31) {
            int k0 = (kt + 1) * 16;
            ra0 = *(const float4*)(emb + (size_t)tok[lr] * 512 + k0 + lc);
            ra1 = *(const float4*)(emb + (size_t)tok[lr + 64] * 512 + k0 + lc);
            rb0 = *(const float4*)(Wih + (size_t)(nbase + lr) * 1024 + k0 + lc);
            rb1 = *(const float4*)(Wih + (size_t)(nbase + lr + 64) * 1024 + k0 + lc);
        }
        tile_fma(As[cur], Bs[cur], tr, tc, acc);
        if (kt < 31) {
            stT(As[cur ^ 1], lr, lc, ra0); stT(As[cur ^ 1], lr + 64, lc, ra1);
            stT(Bs[cur ^ 1], lr, lc, rb0); stT(Bs[cur ^ 1], lr + 64, lc, rb1);
        }
        __syncthreads();
        cur ^= 1;
    }
    #pragma unroll
    for (int i = 0; i < 8; i++) {
        int b = (i < 4) ? tr * 4 + i : 64 + tr * 4 + (i - 4);
        float* dst = g_Gpre + ((size_t)t * 128 + b) * 2048;
        const float* cw = g_ctxW + (size_t)b * 2048;
        #pragma unroll
        for (int j = 0; j < 4; j++) {
            int nc = nbase + ((j >> 1) << 6) + tc * 4 + ((j & 1) << 1);
            float2 v = unpack2(acc[i][j]);
            dst[nc] = v.x + cw[nc];
            dst[nc + 1] = v.y + cw[nc + 1];
        }
    }
}

// ---------------- persistent LSTM chain: 32 ntiles(64N) x 4 ksplits(128K) -------
__global__ void __launch_bounds__(256, 1) lstm_chain(const float* __restrict__ elhs,
                                                     const float* __restrict__ Whh) {
    __shared__ float SB[128 * 64];       // resident B: [k 0..127][n 0..63] = 32KB
    __shared__ float As[2][16 * 128];    // A double buffer (16KB)
    int tid = threadIdx.x;
    int nt = blockIdx.x & 31;            // N tile: cols [64nt, 64nt+64)
    int ks = blockIdx.x >> 5;            // K split: [128ks, 128ks+128)
    int nbase = nt * 64;
    int kbeg = ks * 128;
    int tr = tid >> 4, tc = tid & 15;
    int lr = tid >> 2, lc = (tid & 3) << 2;

    // load W_hh tile once: SB[k*64 + n], n local
    #pragma unroll
    for (int i = 0; i < 8; i++) {
        int idx = i * 256 + tid;          // 0..2047 float4 units
        int row = idx >> 5;               // n local 0..63
        int c4 = idx & 31;                // float4 within 128-K slice
        float4 v = *(const float4*)(Whh + (size_t)(nbase + row) * 512 + kbeg + c4 * 4);
        SB[(c4 * 4 + 0) * 64 + row] = v.x;
        SB[(c4 * 4 + 1) * 64 + row] = v.y;
        SB[(c4 * 4 + 2) * 64 + row] = v.z;
        SB[(c4 * 4 + 3) * 64 + row] = v.w;
    }
    unsigned epoch = *(volatile unsigned*)&g_bar_gen;
    __syncthreads();

    for (int t = 0; t < 27; t++) {
        const float* A = (t == 0) ? elhs : (g_H2 + (size_t)(t - 1) * 128 * 512);
        unsigned long long acc[8][2];
        #pragma unroll
        for (int i = 0; i < 8; i++) { acc[i][0] = 0ull; acc[i][1] = 0ull; }

        float4 ra0, ra1;
        ra0 = *(const float4*)(A + (size_t)lr * 512 + kbeg + lc);
        ra1 = *(const float4*)(A + (size_t)(lr + 64) * 512 + kbeg + lc);
        stT(As[0], lr, lc, ra0); stT(As[0], lr + 64, lc, ra1);
        __syncthreads();
        int cur = 0;
        #pragma unroll
        for (int kt = 0; kt < 8; kt++) {
            if (kt < 7) {
                int k0 = kbeg + (kt + 1) * 16;
                ra0 = *(const float4*)(A + (size_t)lr * 512 + k0 + lc);
                ra1 = *(const float4*)(A + (size_t)(lr + 64) * 512 + k0 + lc);
            }
            tile_fma64(As[cur], SB + kt * 16 * 64, tr, tc, acc);
            if (kt < 7) {
                stT(As[cur ^ 1], lr, lc, ra0); stT(As[cur ^ 1], lr + 64, lc, ra1);
            }
            __syncthreads();
            cur ^= 1;
        }
        // write partials: thread covers M rows {tr*4+i, 64+tr*4+i}, N = nbase+tc*4..+3
        #pragma unroll
        for (int i = 0; i < 8; i++) {
            int b = (i < 4) ? tr * 4 + i : 64 + tr * 4 + (i - 4);
            float* dst = g_part + ((size_t)ks * 128 + b) * 2048 + nbase + tc * 4;
            float2 v0 = unpack2(acc[i][0]);
            float2 v1 = unpack2(acc[i][1]);
            dst[0] = v0.x; dst[1] = v0.y; dst[2] = v1.x; dst[3] = v1.y;
        }
        gsync(++epoch);

        #pragma unroll
        for (int e = 0; e < 2; e++) {
            int idx = e * 32768 + blockIdx.x * 256 + tid;
            int b = idx >> 9, j = idx & 511;
            const float* gp = g_Gpre + ((size_t)t * 128 + b) * 2048;
            float gi = gp[j], gf = gp[j + 512], gg = gp[j + 1024], go = gp[j + 1536];
            #pragma unroll
            for (int kk = 0; kk < 4; kk++) {
                const float* pp = g_part + ((size_t)kk * 128 + b) * 2048;
                gi += __ldcg(pp + j);
                gf += __ldcg(pp + j + 512);
                gg += __ldcg(pp + j + 1024);
                go += __ldcg(pp + j + 1536);
            }
            float cprev = (t == 0) ? 0.f : __ldcg(&g_c[(t - 1) & 1][b * 512 + j]);
            float si = 1.f / (1.f + expf(-gi));
            float sf = 1.f / (1.f + expf(-gf));
            float so = 1.f / (1.f + expf(-go));
            float c2 = sf * cprev + si * tanhf(gg);
            float h2 = so * tanhf(c2);
            g_c[t & 1][b * 512 + j] = c2;
            size_t hidx = (size_t)t * 128 * 512 + b * 512 + j;
            g_H2[hidx] = h2;
            g_Ah[hidx] = __float2half_rn(h2);
        }
        gsync(++epoch);
    }
}

// ---------------- HMMA logits GEMM: 128x256, k16 mbarrier pipeline (R14) --------
__global__ void __launch_bounds__(512, 1) hmma_logits(const float* __restrict__ bout,
                                                      float* __restrict__ out) {
    extern __shared__ char lsm[];
    int tid = threadIdx.x;
    int lane = tid & 31, wid = tid >> 5;
    int wm = wid & 1, wn = wid >> 1;
    int ntile = blockIdx.x, mtile = blockIdx.y;
    int mbase = mtile * 128, nbase = ntile * 256;

    const __half* gA = g_Ah + (size_t)mbase * 512;
    const __half* gB = g_Wh + (size_t)nbase * 512;

    int rA = tid >> 1, kbA = tid & 1;
    int rB = tid >> 1, kbB = tid & 1;
    uint32_t dA = (uint32_t)(((rA >> 3) * 2 + kbA) * 128 + (rA & 7) * 16);
    uint32_t dB = (uint32_t)(((rB >> 3) * 2 + kbB) * 128 + (rB & 7) * 16);
    size_t sA = (size_t)rA * 512 + kbA * 8;
    size_t sB = (size_t)rB * 512 + kbB * 8;
    uint32_t sbase = smem_u32(lsm);
    uint32_t mbb = sbase + 36864u;

    if (tid == 0) {
        #pragma unroll
        for (int s = 0; s < 3; s++) {
            MB_INIT(mbb + 8u * s, 512);
            MB_INIT(mbb + 24u + 8u * s, 16);
        }
    }
    __syncthreads();

    uint32_t a_lane = (uint32_t)(((((lane >> 3) & 1) * 2 + (lane >> 4)) * 128) + (lane & 7) * 16);
    uint32_t b_lane = (uint32_t)((((lane >> 3) & 3) * 128) + (lane & 7) * 16);

    float d[4][4][4];
    #pragma unroll
    for (int i = 0; i < 4; i++)
        #pragma unroll
        for (int j = 0; j < 4; j++)
            #pragma unroll
            for (int q = 0; q < 4; q++) d[i][j][q] = 0.f;

    auto produce = [&](int C) {
        int st = C % 3;
        int rr = C / 3;
        if (rr > 0) mbar_wait(mbb + 24u + 8u * st, (unsigned)((rr - 1) & 1));
        uint32_t sb = sbase + (uint32_t)st * 12288u;
        size_t ko = (size_t)C * 16;
        cp16(sb + 4096u + dB, gB + sB + ko);
        if (tid < 256) cp16(sb + dA, gA + sA + ko);
        CP_MBAR_ARRIVE(mbb + 8u * st);
    };

    produce(0);
    produce(1);

    for (int c = 0; c < 32; c++) {
        if (c + 2 < 32) produce(c + 2);
        int st = c % 3;
        mbar_wait(mbb + 8u * st, (unsigned)((c / 3) & 1));
        uint32_t sb = sbase + (uint32_t)st * 12288u;

        uint32_t a[4][4], b[4][2];
        uint32_t abase = sb + a_lane;
        uint32_t bbase = sb + 4096u + b_lane;
        #pragma unroll
        for (int mt = 0; mt < 4; mt++) ldm_x4(a[mt], abase + (uint32_t)((wm * 4 + mt) * 512));
        #pragma unroll
        for (int p = 0; p < 2; p++) {
            uint32_t rr[4];
            ldm_x4(rr, bbase + (uint32_t)((wn * 4 + 2 * p) * 256));
            b[2 * p][0] = rr[0]; b[2 * p][1] = rr[1];
            b[2 * p + 1][0] = rr[2]; b[2 * p + 1][1] = rr[3];
        }
        #pragma unroll
        for (int mt = 0; mt < 4; mt++)
            #pragma unroll
            for (int nt = 0; nt < 4; nt++) mma_fp16(d[mt][nt], a[mt], b[nt]);

        if (lane == 0) MB_ARRIVE(mbb + 24u + 8u * st);
    }

    // epilogue: logits + per-(row,ntile) max
    __syncthreads();
    unsigned* srow = (unsigned*)lsm;
    if (tid < 128) srow[tid] = 0u;
    __syncthreads();

    float rmax[4][2];
    #pragma unroll
    for (int mt = 0; mt < 4; mt++) { rmax[mt][0] = -3.4e38f; rmax[mt][1] = -3.4e38f; }
    #pragma unroll
    for (int nt = 0; nt < 4; nt++) {
        int n = nbase + wn * 32 + nt * 8 + (lane & 3) * 2;
        if (n >= Vv) continue;
        float bx = bout[n], by = bout[n + 1];
        #pragma unroll
        for (int mt = 0; mt < 4; mt++) {
            int m0 = wm * 64 + mt * 16 + (lane >> 2);
            size_t row0 = (size_t)(m0 * 27 + mtile) * Vv;
            size_t row8 = (size_t)((m0 + 8) * 27 + mtile) * Vv;
            float2 v0 = make_float2(d[mt][nt][0] + bx, d[mt][nt][1] + by);
            float2 v1 = make_float2(d[mt][nt][2] + bx, d[mt][nt][3] + by);
            *(float2*)(out + row0 + n) = v0;
            *(float2*)(out + row8 + n) = v1;
            rmax[mt][0] = fmaxf(rmax[mt][0], fmaxf(v0.x, v0.y));
            rmax[mt][1] = fmaxf(rmax[mt][1], fmaxf(v1.x, v1.y));
        }
    }
    #pragma unroll
    for (int mt = 0; mt < 4; mt++) {
        int q = lane >> 2;
        atomicMax(&srow[wm * 64 + mt * 16 + q],     fenc(rmax[mt][0]));
        atomicMax(&srow[wm * 64 + mt * 16 + q + 8], fenc(rmax[mt][1]));
    }
    __syncthreads();
    if (tid < 128)
        g_tilemax[(size_t)(tid * 27 + mtile) * TMSTRIDE + ntile] = fdec(srow[tid]);
}

// ---------------- argmax: tile-max guided scan + exact-fp32 recheck -------------
__global__ void argmax_exact(const float* __restrict__ logits, float* __restrict__ preds,
                             const float* __restrict__ Wout, const float* __restrict__ bout) {
    __shared__ float sv[256];
    __shared__ float hrow[512];
    __shared__ int scand[64];
    __shared__ int tlist[32];
    __shared__ int ncand, ntl;
    __shared__ float bestv;
    __shared__ int besti;
    int rrow = blockIdx.x;
    int tid = threadIdx.x;
    int b = rrow / 27, t = rrow % 27;
    const float* row = logits + (size_t)rrow * Vv;

    float v = (tid < NT256) ? g_tilemax[(size_t)rrow * TMSTRIDE + tid] : -3.4e38f;
    sv[tid] = v;
    __syncthreads();
    for (int o = 128; o; o >>= 1) {
        if (tid < o) sv[tid] = fmaxf(sv[tid], sv[tid + o]);
        __syncthreads();
    }
    float thr = sv[0] - 1e-3f;

    const float* h = g_H2 + ((size_t)t * 128 + b) * 512;
    hrow[tid] = h[tid];
    hrow[tid + 256] = h[tid + 256];
    if (tid == 0) { ncand = 0; ntl = 0; bestv = -3.4e38f; besti = 0x7fffffff; }
    __syncthreads();

    if (tid < NT256 && v >= thr) {
        int p = atomicAdd(&ntl, 1);
        if (p < 32) tlist[p] = tid;
    }
    __syncthreads();
    int ntiles = ntl < 32 ? ntl : 32;

    for (int ti = 0; ti < ntiles; ti++) {
        int n = tlist[ti] * 256 + tid;
        if (n < Vv) {
            float lv = row[n];
            if (lv >= thr) {
                int p = atomicAdd(&ncand, 1);
                if (p < 64) scand[p] = n;
            }
        }
    }
    __syncthreads();
    int nc = ncand < 64 ? ncand : 64;

    for (int ci = 0; ci < nc; ci++) {
        int idx = scand[ci];
        const float* wr = Wout + (size_t)idx * 512;
        float p = 0.f;
        for (int k = tid; k < 512; k += 256) p += hrow[k] * wr[k];
        sv[tid] = p;
        __syncthreads();
        for (int o = 128; o; o >>= 1) {
            if (tid < o) sv[tid] += sv[tid + o];
            __syncthreads();
        }
        if (tid == 0) {
            float ev = sv[0] + bout[idx];
            if (ev > bestv || (ev == bestv && idx < besti)) { bestv = ev; besti = idx; }
        }
        __syncthreads();
    }
    if (tid == 0) preds[rrow] = (float)besti;
}

// -------------------------------------------------------------------------------
extern "C" void kernel_launch(void* const* d_in, const int* in_sizes, int n_in,
                              void* d_out, int out_size) {
    const float* elhs    = (const float*)d_in[0];
    const float* enc     = (const float*)d_in[1];
    const int*   targets = (const int*)d_in[2];
    const float* emb     = (const float*)d_in[3];
    const float* W1      = (const float*)d_in[4];
    const float* W2      = (const float*)d_in[6];
    const float* W3      = (const float*)d_in[8];
    const float* W4      = (const float*)d_in[10];
    const float* w_att   = (const float*)d_in[12];
    const float* W_ih    = (const float*)d_in[13];
    const float* W_hh    = (const float*)d_in[14];
    const float* b_ih    = (const float*)d_in[15];
    const float* b_hh    = (const float*)d_in[16];
    const float* W_out   = (const float*)d_in[17];
    const float* b_out   = (const float*)d_in[18];
    float* out = (float*)d_out;

    // 1: fused convW + fold + attention + ctxW
    fused_prep<<<NBLK, 256>>>(w_att, W4, W3, W2, W1, enc, W_out, W_ih, b_ih, b_hh);

    // 2: Gpre (emb part only, K=512, occ-2, 432 blocks)
    gpre_gemm<<<dim3(16, 27), 256>>>(targets, emb, W_ih);

    // 3: LSTM chain (32 ntiles x 4 ksplits, halved partials traffic)
    lstm_chain<<<NBLK, 256>>>(elhs, W_hh);

    // 4: logits GEMM (R14 config: k16 mbarrier pipeline)  [profiled slot]
    hmma_logits<<<dim3(NT256, 27), 512, LOG_SMEM>>>(b_out, out);

    // 5: argmax (tile-max guided, 256-wide tiles)
    long long main_sz = (long long)3456 * Vv;
    if ((long long)out_size > main_sz)
        argmax_exact<<<3456, 256>>>(out, out + main_sz, W_out, b_out);
}

// round 17
// speedup vs baseline: 1.1261x; 1.0843x over previous
#include <cuda_runtime.h>
#include <cuda_fp16.h>
#include <math.h>
#include <stdint.h>

// ----------------------------------------------------------------------------
// DecoderLSTMWithAttention — R17:
//   - gpre moved to fp16 HMMA (clone of the measured-best R14 logits pipeline,
//     token-gathered A, ctxW-adding epilogue). Error budget: emb@WihA part of
//     the gates is ~6% of gate magnitude; fp16 rounding adds ~3e-5 relative
//     -> output rel_err unchanged.
//   - prep phase A now also converts emb + Wih[:, :512] to fp16.
//   - chain (R16), logits (R14 config), tile-max argmax unchanged.
// ----------------------------------------------------------------------------

#define Bb 128
#define Hh 512
#define Tt 27
#define Vv 30000
#define NBLK 128
#define VPAD 30208
#define NT256 118
#define TMSTRIDE 120
#define LOG_SMEM (3 * 12288 + 64)

// scratch (device globals: no allocations allowed)
__device__ float g_v0[512];
__device__ float g_v1[512];
__device__ float g_q[512];
__device__ float g_ctx[128 * 512];
__device__ float g_ctxW[128 * 2048];
__device__ float g_Gpre[27u * 128u * 2048u];
__device__ float g_H2[27u * 128u * 512u];
__device__ float g_c[2][128 * 512];
__device__ float g_part[4u * 128u * 2048u];
__device__ unsigned g_bar_cnt;
__device__ unsigned g_bar_gen;
__device__ float g_tilemax[3456u * TMSTRIDE];
__device__ __half g_Ah[3456u * 512u];
__device__ __half g_Wh[(unsigned)VPAD * 512u];
__device__ __half g_Eh[(unsigned)Vv * 512u];
__device__ __half g_WAh[2048u * 512u];

// ---------------- packed fp32x2 helpers ----------------
__device__ __forceinline__ unsigned long long pack2(float x) {
    unsigned long long r;
    asm("mov.b64 %0, {%1, %1};" : "=l"(r) : "f"(x));
    return r;
}
__device__ __forceinline__ void ffma2(unsigned long long& d, unsigned long long a, unsigned long long b) {
    asm("fma.rn.f32x2 %0, %1, %2, %0;" : "+l"(d) : "l"(a), "l"(b));
}
__device__ __forceinline__ float2 unpack2(unsigned long long v) {
    float lo, hi;
    asm("mov.b64 {%0, %1}, %2;" : "=f"(lo), "=f"(hi) : "l"(v));
    return make_float2(lo, hi);
}

// ---------------- ptx helpers ----------------------------------------------------
__device__ __forceinline__ uint32_t smem_u32(const void* p) {
    uint32_t a;
    asm("{ .reg .u64 t; cvta.to.shared.u64 t, %1; cvt.u32.u64 %0, t; }" : "=r"(a) : "l"(p));
    return a;
}
__device__ __forceinline__ void cp16(uint32_t dst, const void* src) {
    asm volatile("cp.async.cg.shared.global [%0], [%1], 16;" :: "r"(dst), "l"(src));
}
__device__ __forceinline__ void ldm_x4(uint32_t* r, uint32_t addr) {
    asm volatile("ldmatrix.sync.aligned.m8n8.x4.shared.b16 {%0,%1,%2,%3}, [%4];"
        : "=r"(r[0]), "=r"(r[1]), "=r"(r[2]), "=r"(r[3]) : "r"(addr));
}
__device__ __forceinline__ void mma_fp16(float* d, const uint32_t* a, const uint32_t* b) {
    asm volatile("mma.sync.aligned.m16n8k16.row.col.f32.f16.f16.f32 "
        "{%0,%1,%2,%3}, {%4,%5,%6,%7}, {%8,%9}, {%0,%1,%2,%3};"
        : "+f"(d[0]), "+f"(d[1]), "+f"(d[2]), "+f"(d[3])
        : "r"(a[0]), "r"(a[1]), "r"(a[2]), "r"(a[3]), "r"(b[0]), "r"(b[1]));
}
__device__ __forceinline__ unsigned fenc(float x) {
    int i = __float_as_int(x);
    return (i >= 0) ? ((unsigned)i | 0x80000000u) : ~(unsigned)i;
}
__device__ __forceinline__ float fdec(unsigned e) {
    int i = (e & 0x80000000u) ? (int)(e & 0x7fffffffu) : ~(int)e;
    return __int_as_float(i);
}

// ---------------- mbarrier helpers ----------------------------------------------
#define MB_INIT(a, c) asm volatile("mbarrier.init.shared.b64 [%0], %1;" :: "r"(a), "r"(c) : "memory")
#define MB_ARRIVE(a)  asm volatile("mbarrier.arrive.shared.b64 _, [%0];" :: "r"(a) : "memory")
#define CP_MBAR_ARRIVE(a) asm volatile("cp.async.mbarrier.arrive.noinc.shared.b64 [%0];" :: "r"(a) : "memory")
__device__ __forceinline__ void mbar_wait(uint32_t mbar, uint32_t parity) {
    uint32_t done;
    asm volatile(
        "{\n\t.reg .pred p;\n\t"
        "mbarrier.try_wait.parity.acquire.cta.shared::cta.b64 p, [%1], %2;\n\t"
        "selp.b32 %0, 1, 0, p;\n\t}"
        : "=r"(done) : "r"(mbar), "r"(parity) : "memory");
    if (!done) {
        asm volatile(
            "{\n\t.reg .pred P1;\n\t"
            "W_%=:\n\t"
            "mbarrier.try_wait.parity.acquire.cta.shared::cta.b64 P1, [%0], %1, 0x989680;\n\t"
            "@P1 bra.uni D_%=;\n\t"
            "bra.uni W_%=;\n\t"
            "D_%=:\n\t}"
            :: "r"(mbar), "r"(parity) : "memory");
    }
}

// ---------------- software grid barrier ------------------------------------------
__device__ __forceinline__ void gsync(unsigned target) {
    __syncthreads();
    if (threadIdx.x == 0) {
        __threadfence();
        unsigned prev = atomicAdd(&g_bar_cnt, 1u);
        if (prev == NBLK - 1) {
            g_bar_cnt = 0;
            __threadfence();
            *(volatile unsigned*)&g_bar_gen = target;
        } else {
            volatile unsigned* vg = (volatile unsigned*)&g_bar_gen;
            while ((int)(*vg - target) < 0) {}
        }
        __threadfence();
    }
    __syncthreads();
}

// ---------------- FFMA2 micro-kernel (chain, 128M x 64N) -------------------------
__device__ __forceinline__ void tile_fma64(const float* As, const float* Bs, int tr, int tc,
                                           unsigned long long acc[8][2]) {
    #pragma unroll
    for (int kk = 0; kk < 16; kk++) {
        float4 a0 = *(const float4*)(As + kk * 128 + tr * 4);
        float4 a1 = *(const float4*)(As + kk * 128 + 64 + tr * 4);
        ulonglong2 b0 = *(const ulonglong2*)(Bs + kk * 64 + tc * 4);
        unsigned long long pb0 = b0.x, pb1 = b0.y;
        float av[8] = {a0.x, a0.y, a0.z, a0.w, a1.x, a1.y, a1.z, a1.w};
        #pragma unroll
        for (int i = 0; i < 8; i++) {
            unsigned long long pa = pack2(av[i]);
            ffma2(acc[i][0], pa, pb0);
            ffma2(acc[i][1], pa, pb1);
        }
    }
}
__device__ __forceinline__ void stT(float* S, int r, int lc, float4 v) {
    float* d = S + r;
    d[(lc + 0) * 128] = v.x;
    d[(lc + 1) * 128] = v.y;
    d[(lc + 2) * 128] = v.z;
    d[(lc + 3) * 128] = v.w;
}

// ---------------- fused prep: conversions -> matvec fold -> attention -> ctxW ---
__global__ void __launch_bounds__(256) fused_prep(
    const float* __restrict__ w_att, const float* __restrict__ W4,
    const float* __restrict__ W3, const float* __restrict__ W2,
    const float* __restrict__ W1, const float* __restrict__ enc,
    const float* __restrict__ Wout, const float* __restrict__ Wih,
    const float* __restrict__ bih, const float* __restrict__ bhh,
    const float* __restrict__ emb) {
    __shared__ float S[1024];
    __shared__ float Wt[16 * 512];
    int tid = threadIdx.x, bid = blockIdx.x;
    unsigned gen0 = *(volatile unsigned*)&g_bar_gen;

    // phase A: conversions to fp16
    {
        int stride = NBLK * 256 * 4;
        int nW = Vv * 512;
        for (int i0 = (bid * 256 + tid) * 4; i0 < VPAD * 512; i0 += stride) {
            if (i0 + 3 < nW) {
                float4 v = *(const float4*)(Wout + i0);
                __half2* dp = (__half2*)(g_Wh + i0);
                dp[0] = __floats2half2_rn(v.x, v.y);
                dp[1] = __floats2half2_rn(v.z, v.w);
            } else {
                #pragma unroll
                for (int u = 0; u < 4; u++) {
                    int i = i0 + u;
                    g_Wh[i] = __float2half_rn(i < nW ? Wout[i] : 0.f);
                }
            }
        }
        for (int i0 = (bid * 256 + tid) * 4; i0 < Vv * 512; i0 += stride) {
            float4 v = *(const float4*)(emb + i0);
            __half2* dp = (__half2*)(g_Eh + i0);
            dp[0] = __floats2half2_rn(v.x, v.y);
            dp[1] = __floats2half2_rn(v.z, v.w);
        }
        for (int i0 = (bid * 256 + tid) * 4; i0 < 2048 * 512; i0 += stride) {
            int n = i0 >> 9, k = i0 & 511;
            float4 v = *(const float4*)(Wih + (size_t)n * 1024 + k);
            __half2* dp = (__half2*)(g_WAh + i0);
            dp[0] = __floats2half2_rn(v.x, v.y);
            dp[1] = __floats2half2_rn(v.z, v.w);
        }
    }

    // phases 0..3: fold q
    const float* Ws[4] = {W4, W3, W2, W1};
    #pragma unroll 1
    for (int p = 0; p < 4; p++) {
        const float* W = Ws[p];
        int stride = (p == 3) ? 1024 : 512;
        const float* vin = (p == 0) ? w_att : ((p == 2) ? g_v1 : g_v0);
        float* vout = (p == 0) ? g_v0 : ((p == 1) ? g_v1 : ((p == 2) ? g_v0 : g_q));
        int k = bid * 4 + (tid & 3);
        int s = tid >> 2;
        float a = 0.f;
        #pragma unroll
        for (int u = 0; u < 8; u++) {
            int j = s * 8 + u;
            a += __ldcg(vin + j) * W[(size_t)j * stride + k];
        }
        S[tid] = a;
        __syncthreads();
        if (tid < 4) {
            float acc = 0.f;
            for (int s2 = 0; s2 < 64; s2++) acc += S[tid + 4 * s2];
            vout[bid * 4 + tid] = acc;
        }
        gsync(gen0 + 1 + p);
    }

    // attention (b = bid)
    {
        float* sq = &S[0];
        float* sc = &S[512];
        int b = bid;
        sq[tid] = __ldcg(g_q + tid);
        sq[tid + 256] = __ldcg(g_q + tid + 256);
        __syncthreads();
        int w = tid >> 5, lane = tid & 31;
        for (int s = w; s < 80; s += 8) {
            const float* e = enc + ((size_t)b * 80 + s) * 512;
            float acc = 0.f;
            for (int k = lane; k < 512; k += 32) acc += e[k] * sq[k];
            #pragma unroll
            for (int o = 16; o; o >>= 1) acc += __shfl_xor_sync(0xffffffffu, acc, o);
            if (lane == 0) sc[s] = acc;
        }
        __syncthreads();
        if (tid < 32) {
            float m = -1e30f;
            for (int s = tid; s < 80; s += 32) m = fmaxf(m, sc[s]);
            #pragma unroll
            for (int o = 16; o; o >>= 1) m = fmaxf(m, __shfl_xor_sync(0xffffffffu, m, o));
            float sum = 0.f;
            for (int s = tid; s < 80; s += 32) { float e = expf(sc[s] - m); sc[s] = e; sum += e; }
            #pragma unroll
            for (int o = 16; o; o >>= 1) sum += __shfl_xor_sync(0xffffffffu, sum, o);
            float inv = 1.f / sum;
            for (int s = tid; s < 80; s += 32) sc[s] *= inv;
        }
        __syncthreads();
        for (int k = tid; k < 512; k += 256) {
            float a = 0.f;
            #pragma unroll 8
            for (int s = 0; s < 80; s++) a += sc[s] * enc[((size_t)b * 80 + s) * 512 + k];
            g_ctx[b * 512 + k] = a;
        }
    }
    gsync(gen0 + 5);

    // ctxW: block bid computes ctxW[:, 16*bid .. +16)
    {
        int nb = bid * 16;
        for (int i = 0; i < 32; i++) {
            int idx = i * 256 + tid;
            int row = idx >> 9, col = idx & 511;
            Wt[row * 512 + col] = Wih[(size_t)(nb + row) * 1024 + 512 + col];
        }
        __syncthreads();
        int nl = tid & 15;
        int bg = tid >> 4;
        float bias = bih[nb + nl] + bhh[nb + nl];
        #pragma unroll
        for (int i = 0; i < 8; i++) {
            int b = bg * 8 + i;
            const float4* cr = (const float4*)(g_ctx + b * 512);
            const float4* wr = (const float4*)(Wt + nl * 512);
            float a0 = 0.f, a1 = 0.f, a2 = 0.f, a3 = 0.f;
            #pragma unroll 16
            for (int q = 0; q < 128; q++) {
                float4 c = cr[q];
                float4 w = wr[q];
                a0 += c.x * w.x; a1 += c.y * w.y; a2 += c.z * w.z; a3 += c.w * w.w;
            }
            g_ctxW[b * 2048 + nb + nl] = (a0 + a1) + (a2 + a3) + bias;
        }
    }
}

// ---------------- gpre: fp16 HMMA, 128x256 tile, k16 mbarrier pipeline ----------
// grid (8, 27): ntile 0..7 (N=2048), mtile = t. A rows gathered by token.
__global__ void __launch_bounds__(512, 1) gpre_hmma(const int* __restrict__ targets) {
    extern __shared__ char lsm[];
    __shared__ int tok[128];
    int tid = threadIdx.x;
    int lane = tid & 31, wid = tid >> 5;
    int wm = wid & 1, wn = wid >> 1;
    int ntile = blockIdx.x, t = blockIdx.y;
    int nbase = ntile * 256;

    if (tid < 128) tok[tid] = targets[tid * 28 + t];

    int rA = tid >> 1, kbA = tid & 1;
    int rB = tid >> 1, kbB = tid & 1;
    uint32_t dA = (uint32_t)(((rA >> 3) * 2 + kbA) * 128 + (rA & 7) * 16);
    uint32_t dB = (uint32_t)(((rB >> 3) * 2 + kbB) * 128 + (rB & 7) * 16);
    size_t sB = (size_t)(nbase + rB) * 512 + kbB * 8;
    uint32_t sbase = smem_u32(lsm);
    uint32_t mbb = sbase + 36864u;

    if (tid == 0) {
        #pragma unroll
        for (int s = 0; s < 3; s++) {
            MB_INIT(mbb + 8u * s, 512);
            MB_INIT(mbb + 24u + 8u * s, 16);
        }
    }
    __syncthreads();
    size_t sA = (tid < 256) ? ((size_t)tok[rA] * 512 + kbA * 8) : 0;

    uint32_t a_lane = (uint32_t)(((((lane >> 3) & 1) * 2 + (lane >> 4)) * 128) + (lane & 7) * 16);
    uint32_t b_lane = (uint32_t)((((lane >> 3) & 3) * 128) + (lane & 7) * 16);

    float d[4][4][4];
    #pragma unroll
    for (int i = 0; i < 4; i++)
        #pragma unroll
        for (int j = 0; j < 4; j++)
            #pragma unroll
            for (int q = 0; q < 4; q++) d[i][j][q] = 0.f;

    auto produce = [&](int C) {
        int st = C % 3;
        int rr = C / 3;
        if (rr > 0) mbar_wait(mbb + 24u + 8u * st, (unsigned)((rr - 1) & 1));
        uint32_t sb = sbase + (uint32_t)st * 12288u;
        size_t ko = (size_t)C * 16;
        cp16(sb + 4096u + dB, g_WAh + sB + ko);
        if (tid < 256) cp16(sb + dA, g_Eh + sA + ko);
        CP_MBAR_ARRIVE(mbb + 8u * st);
    };

    produce(0);
    produce(1);

    for (int c = 0; c < 32; c++) {
        if (c + 2 < 32) produce(c + 2);
        int st = c % 3;
        mbar_wait(mbb + 8u * st, (unsigned)((c / 3) & 1));
        uint32_t sb = sbase + (uint32_t)st * 12288u;

        uint32_t a[4][4], b[4][2];
        uint32_t abase = sb + a_lane;
        uint32_t bbase = sb + 4096u + b_lane;
        #pragma unroll
        for (int mt = 0; mt < 4; mt++) ldm_x4(a[mt], abase + (uint32_t)((wm * 4 + mt) * 512));
        #pragma unroll
        for (int p = 0; p < 2; p++) {
            uint32_t rr[4];
            ldm_x4(rr, bbase + (uint32_t)((wn * 4 + 2 * p) * 256));
            b[2 * p][0] = rr[0]; b[2 * p][1] = rr[1];
            b[2 * p + 1][0] = rr[2]; b[2 * p + 1][1] = rr[3];
        }
        #pragma unroll
        for (int mt = 0; mt < 4; mt++)
            #pragma unroll
            for (int nt = 0; nt < 4; nt++) mma_fp16(d[mt][nt], a[mt], b[nt]);

        if (lane == 0) MB_ARRIVE(mbb + 24u + 8u * st);
    }

    // epilogue: Gpre[t*128+m][n] = d + ctxW[m][n]
    #pragma unroll
    for (int nt = 0; nt < 4; nt++) {
        int n = nbase + wn * 32 + nt * 8 + (lane & 3) * 2;
        #pragma unroll
        for (int mt = 0; mt < 4; mt++) {
            int m0 = wm * 64 + mt * 16 + (lane >> 2);
            float2 c0 = *(const float2*)(g_ctxW + (size_t)m0 * 2048 + n);
            float2 c8 = *(const float2*)(g_ctxW + (size_t)(m0 + 8) * 2048 + n);
            float* d0 = g_Gpre + ((size_t)t * 128 + m0) * 2048 + n;
            float* d8 = g_Gpre + ((size_t)t * 128 + m0 + 8) * 2048 + n;
            *(float2*)d0 = make_float2(d[mt][nt][0] + c0.x, d[mt][nt][1] + c0.y);
            *(float2*)d8 = make_float2(d[mt][nt][2] + c8.x, d[mt][nt][3] + c8.y);
        }
    }
}

// ---------------- persistent LSTM chain: 32 ntiles(64N) x 4 ksplits(128K) -------
__global__ void __launch_bounds__(256, 1) lstm_chain(const float* __restrict__ elhs,
                                                     const float* __restrict__ Whh) {
    __shared__ float SB[128 * 64];
    __shared__ float As[2][16 * 128];
    int tid = threadIdx.x;
    int nt = blockIdx.x & 31;
    int ks = blockIdx.x >> 5;
    int nbase = nt * 64;
    int kbeg = ks * 128;
    int tr = tid >> 4, tc = tid & 15;
    int lr = tid >> 2, lc = (tid & 3) << 2;

    #pragma unroll
    for (int i = 0; i < 8; i++) {
        int idx = i * 256 + tid;
        int row = idx >> 5;
        int c4 = idx & 31;
        float4 v = *(const float4*)(Whh + (size_t)(nbase + row) * 512 + kbeg + c4 * 4);
        SB[(c4 * 4 + 0) * 64 + row] = v.x;
        SB[(c4 * 4 + 1) * 64 + row] = v.y;
        SB[(c4 * 4 + 2) * 64 + row] = v.z;
        SB[(c4 * 4 + 3) * 64 + row] = v.w;
    }
    unsigned epoch = *(volatile unsigned*)&g_bar_gen;
    __syncthreads();

    for (int t = 0; t < 27; t++) {
        const float* A = (t == 0) ? elhs : (g_H2 + (size_t)(t - 1) * 128 * 512);
        unsigned long long acc[8][2];
        #pragma unroll
        for (int i = 0; i < 8; i++) { acc[i][0] = 0ull; acc[i][1] = 0ull; }

        float4 ra0, ra1;
        ra0 = *(const float4*)(A + (size_t)lr * 512 + kbeg + lc);
        ra1 = *(const float4*)(A + (size_t)(lr + 64) * 512 + kbeg + lc);
        stT(As[0], lr, lc, ra0); stT(As[0], lr + 64, lc, ra1);
        __syncthreads();
        int cur = 0;
        #pragma unroll
        for (int kt = 0; kt < 8; kt++) {
            if (kt < 7) {
                int k0 = kbeg + (kt + 1) * 16;
                ra0 = *(const float4*)(A + (size_t)lr * 512 + k0 + lc);
                ra1 = *(const float4*)(A + (size_t)(lr + 64) * 512 + k0 + lc);
            }
            tile_fma64(As[cur], SB + kt * 16 * 64, tr, tc, acc);
            if (kt < 7) {
                stT(As[cur ^ 1], lr, lc, ra0); stT(As[cur ^ 1], lr + 64, lc, ra1);
            }
            __syncthreads();
            cur ^= 1;
        }
        #pragma unroll
        for (int i = 0; i < 8; i++) {
            int b = (i < 4) ? tr * 4 + i : 64 + tr * 4 + (i - 4);
            float* dst = g_part + ((size_t)ks * 128 + b) * 2048 + nbase + tc * 4;
            float2 v0 = unpack2(acc[i][0]);
            float2 v1 = unpack2(acc[i][1]);
            dst[0] = v0.x; dst[1] = v0.y; dst[2] = v1.x; dst[3] = v1.y;
        }
        gsync(++epoch);

        #pragma unroll
        for (int e = 0; e < 2; e++) {
            int idx = e * 32768 + blockIdx.x * 256 + tid;
            int b = idx >> 9, j = idx & 511;
            const float* gp = g_Gpre + ((size_t)t * 128 + b) * 2048;
            float gi = gp[j], gf = gp[j + 512], gg = gp[j + 1024], go = gp[j + 1536];
            #pragma unroll
            for (int kk = 0; kk < 4; kk++) {
                const float* pp = g_part + ((size_t)kk * 128 + b) * 2048;
                gi += __ldcg(pp + j);
                gf += __ldcg(pp + j + 512);
                gg += __ldcg(pp + j + 1024);
                go += __ldcg(pp + j + 1536);
            }
            float cprev = (t == 0) ? 0.f : __ldcg(&g_c[(t - 1) & 1][b * 512 + j]);
            float si = 1.f / (1.f + expf(-gi));
            float sf = 1.f / (1.f + expf(-gf));
            float so = 1.f / (1.f + expf(-go));
            float c2 = sf * cprev + si * tanhf(gg);
            float h2 = so * tanhf(c2);
            g_c[t & 1][b * 512 + j] = c2;
            size_t hidx = (size_t)t * 128 * 512 + b * 512 + j;
            g_H2[hidx] = h2;
            g_Ah[hidx] = __float2half_rn(h2);
        }
        gsync(++epoch);
    }
}

// ---------------- HMMA logits GEMM: 128x256, k16 mbarrier pipeline (R14) --------
__global__ void __launch_bounds__(512, 1) hmma_logits(const float* __restrict__ bout,
                                                      float* __restrict__ out) {
    extern __shared__ char lsm[];
    int tid = threadIdx.x;
    int lane = tid & 31, wid = tid >> 5;
    int wm = wid & 1, wn = wid >> 1;
    int ntile = blockIdx.x, mtile = blockIdx.y;
    int mbase = mtile * 128, nbase = ntile * 256;

    const __half* gA = g_Ah + (size_t)mbase * 512;
    const __half* gB = g_Wh + (size_t)nbase * 512;

    int rA = tid >> 1, kbA = tid & 1;
    int rB = tid >> 1, kbB = tid & 1;
    uint32_t dA = (uint32_t)(((rA >> 3) * 2 + kbA) * 128 + (rA & 7) * 16);
    uint32_t dB = (uint32_t)(((rB >> 3) * 2 + kbB) * 128 + (rB & 7) * 16);
    size_t sA = (size_t)rA * 512 + kbA * 8;
    size_t sB = (size_t)rB * 512 + kbB * 8;
    uint32_t sbase = smem_u32(lsm);
    uint32_t mbb = sbase + 36864u;

    if (tid == 0) {
        #pragma unroll
        for (int s = 0; s < 3; s++) {
            MB_INIT(mbb + 8u * s, 512);
            MB_INIT(mbb + 24u + 8u * s, 16);
        }
    }
    __syncthreads();

    uint32_t a_lane = (uint32_t)(((((lane >> 3) & 1) * 2 + (lane >> 4)) * 128) + (lane & 7) * 16);
    uint32_t b_lane = (uint32_t)((((lane >> 3) & 3) * 128) + (lane & 7) * 16);

    float d[4][4][4];
    #pragma unroll
    for (int i = 0; i < 4; i++)
        #pragma unroll
        for (int j = 0; j < 4; j++)
            #pragma unroll
            for (int q = 0; q < 4; q++) d[i][j][q] = 0.f;

    auto produce = [&](int C) {
        int st = C % 3;
        int rr = C / 3;
        if (rr > 0) mbar_wait(mbb + 24u + 8u * st, (unsigned)((rr - 1) & 1));
        uint32_t sb = sbase + (uint32_t)st * 12288u;
        size_t ko = (size_t)C * 16;
        cp16(sb + 4096u + dB, gB + sB + ko);
        if (tid < 256) cp16(sb + dA, gA + sA + ko);
        CP_MBAR_ARRIVE(mbb + 8u * st);
    };

    produce(0);
    produce(1);

    for (int c = 0; c < 32; c++) {
        if (c + 2 < 32) produce(c + 2);
        int st = c % 3;
        mbar_wait(mbb + 8u * st, (unsigned)((c / 3) & 1));
        uint32_t sb = sbase + (uint32_t)st * 12288u;

        uint32_t a[4][4], b[4][2];
        uint32_t abase = sb + a_lane;
        uint32_t bbase = sb + 4096u + b_lane;
        #pragma unroll
        for (int mt = 0; mt < 4; mt++) ldm_x4(a[mt], abase + (uint32_t)((wm * 4 + mt) * 512));
        #pragma unroll
        for (int p = 0; p < 2; p++) {
            uint32_t rr[4];
            ldm_x4(rr, bbase + (uint32_t)((wn * 4 + 2 * p) * 256));
            b[2 * p][0] = rr[0]; b[2 * p][1] = rr[1];
            b[2 * p + 1][0] = rr[2]; b[2 * p + 1][1] = rr[3];
        }
        #pragma unroll
        for (int mt = 0; mt < 4; mt++)
            #pragma unroll
            for (int nt = 0; nt < 4; nt++) mma_fp16(d[mt][nt], a[mt], b[nt]);

        if (lane == 0) MB_ARRIVE(mbb + 24u + 8u * st);
    }

    // epilogue: logits + per-(row,ntile) max
    __syncthreads();
    unsigned* srow = (unsigned*)lsm;
    if (tid < 128) srow[tid] = 0u;
    __syncthreads();

    float rmax[4][2];
    #pragma unroll
    for (int mt = 0; mt < 4; mt++) { rmax[mt][0] = -3.4e38f; rmax[mt][1] = -3.4e38f; }
    #pragma unroll
    for (int nt = 0; nt < 4; nt++) {
        int n = nbase + wn * 32 + nt * 8 + (lane & 3) * 2;
        if (n >= Vv) continue;
        float bx = bout[n], by = bout[n + 1];
        #pragma unroll
        for (int mt = 0; mt < 4; mt++) {
            int m0 = wm * 64 + mt * 16 + (lane >> 2);
            size_t row0 = (size_t)(m0 * 27 + mtile) * Vv;
            size_t row8 = (size_t)((m0 + 8) * 27 + mtile) * Vv;
            float2 v0 = make_float2(d[mt][nt][0] + bx, d[mt][nt][1] + by);
            float2 v1 = make_float2(d[mt][nt][2] + bx, d[mt][nt][3] + by);
            *(float2*)(out + row0 + n) = v0;
            *(float2*)(out + row8 + n) = v1;
            rmax[mt][0] = fmaxf(rmax[mt][0], fmaxf(v0.x, v0.y));
            rmax[mt][1] = fmaxf(rmax[mt][1], fmaxf(v1.x, v1.y));
        }
    }
    #pragma unroll
    for (int mt = 0; mt < 4; mt++) {
        int q = lane >> 2;
        atomicMax(&srow[wm * 64 + mt * 16 + q],     fenc(rmax[mt][0]));
        atomicMax(&srow[wm * 64 + mt * 16 + q + 8], fenc(rmax[mt][1]));
    }
    __syncthreads();
    if (tid < 128)
        g_tilemax[(size_t)(tid * 27 + mtile) * TMSTRIDE + ntile] = fdec(srow[tid]);
}

// ---------------- argmax: tile-max guided scan + exact-fp32 recheck -------------
__global__ void argmax_exact(const float* __restrict__ logits, float* __restrict__ preds,
                             const float* __restrict__ Wout, const float* __restrict__ bout) {
    __shared__ float sv[256];
    __shared__ float hrow[512];
    __shared__ int scand[64];
    __shared__ int tlist[32];
    __shared__ int ncand, ntl;
    __shared__ float bestv;
    __shared__ int besti;
    int rrow = blockIdx.x;
    int tid = threadIdx.x;
    int b = rrow / 27, t = rrow % 27;
    const float* row = logits + (size_t)rrow * Vv;

    float v = (tid < NT256) ? g_tilemax[(size_t)rrow * TMSTRIDE + tid] : -3.4e38f;
    sv[tid] = v;
    __syncthreads();
    for (int o = 128; o; o >>= 1) {
        if (tid < o) sv[tid] = fmaxf(sv[tid], sv[tid + o]);
        __syncthreads();
    }
    float thr = sv[0] - 1e-3f;

    const float* h = g_H2 + ((size_t)t * 128 + b) * 512;
    hrow[tid] = h[tid];
    hrow[tid + 256] = h[tid + 256];
    if (tid == 0) { ncand = 0; ntl = 0; bestv = -3.4e38f; besti = 0x7fffffff; }
    __syncthreads();

    if (tid < NT256 && v >= thr) {
        int p = atomicAdd(&ntl, 1);
        if (p < 32) tlist[p] = tid;
    }
    __syncthreads();
    int ntiles = ntl < 32 ? ntl : 32;

    for (int ti = 0; ti < ntiles; ti++) {
        int n = tlist[ti] * 256 + tid;
        if (n < Vv) {
            float lv = row[n];
            if (lv >= thr) {
                int p = atomicAdd(&ncand, 1);
                if (p < 64) scand[p] = n;
            }
        }
    }
    __syncthreads();
    int nc = ncand < 64 ? ncand : 64;

    for (int ci = 0; ci < nc; ci++) {
        int idx = scand[ci];
        const float* wr = Wout + (size_t)idx * 512;
        float p = 0.f;
        for (int k = tid; k < 512; k += 256) p += hrow[k] * wr[k];
        sv[tid] = p;
        __syncthreads();
        for (int o = 128; o; o >>= 1) {
            if (tid < o) sv[tid] += sv[tid + o];
            __syncthreads();
        }
        if (tid == 0) {
            float ev = sv[0] + bout[idx];
            if (ev > bestv || (ev == bestv && idx < besti)) { bestv = ev; besti = idx; }
        }
        __syncthreads();
    }
    if (tid == 0) preds[rrow] = (float)besti;
}

// -------------------------------------------------------------------------------
extern "C" void kernel_launch(void* const* d_in, const int* in_sizes, int n_in,
                              void* d_out, int out_size) {
    const float* elhs    = (const float*)d_in[0];
    const float* enc     = (const float*)d_in[1];
    const int*   targets = (const int*)d_in[2];
    const float* emb     = (const float*)d_in[3];
    const float* W1      = (const float*)d_in[4];
    const float* W2      = (const float*)d_in[6];
    const float* W3      = (const float*)d_in[8];
    const float* W4      = (const float*)d_in[10];
    const float* w_att   = (const float*)d_in[12];
    const float* W_ih    = (const float*)d_in[13];
    const float* W_hh    = (const float*)d_in[14];
    const float* b_ih    = (const float*)d_in[15];
    const float* b_hh    = (const float*)d_in[16];
    const float* W_out   = (const float*)d_in[17];
    const float* b_out   = (const float*)d_in[18];
    float* out = (float*)d_out;

    // 1: fused conversions + fold + attention + ctxW
    fused_prep<<<NBLK, 256>>>(w_att, W4, W3, W2, W1, enc, W_out, W_ih, b_ih, b_hh, emb);

    // 2: gpre (fp16 HMMA, token-gathered A, ctxW epilogue)
    gpre_hmma<<<dim3(8, 27), 512, LOG_SMEM>>>(targets);

    // 3: LSTM chain (32 ntiles x 4 ksplits)
    lstm_chain<<<NBLK, 256>>>(elhs, W_hh);

    // 4: logits GEMM (R14 config)  [profiled slot]
    hmma_logits<<<dim3(NT256, 27), 512, LOG_SMEM>>>(b_out, out);

    // 5: argmax (tile-max guided)
    long long main_sz = (long long)3456 * Vv;
    if ((long long)out_size > main_sz)
        argmax_exact<<<3456, 256>>>(out, out + main_sz, W_out, b_out);
}